// round 4
// baseline (speedup 1.0000x reference)
#include <cuda_runtime.h>
#include <math.h>

// BaseRoIHead multi-level RoIAlign (torchvision-style, aligned=False)
// B=2, R=512, C=256, out 7x7, sampling_ratio=2, levels p2..p6 (strides 4..64).
//
//  - one CTA per ROI; blockDim (64, 7): tx = channel-group (float4), ty = out row
//  - sample grid is separable: 14 y + 14 x coords per ROI computed by warp 0
//    (all 32 lanes execute every collective -> no divergent-mask UB)
//  - every gather is a coalesced 64x16B = 1024B row (channels innermost)

#define OUT_HW 7
#define NS (OUT_HW * 2)    // 14 sample coords per axis
#define CCH 256
#define CG  (CCH / 4)      // 64 float4 channel groups

__device__ __forceinline__ float4 f4fma(float s, float4 v, float4 a) {
    a.x = fmaf(s, v.x, a.x); a.y = fmaf(s, v.y, a.y);
    a.z = fmaf(s, v.z, a.z); a.w = fmaf(s, v.w, a.w);
    return a;
}

__global__ __launch_bounds__(CG * OUT_HW) void roialign_fpn_kernel(
    const float* __restrict__ p2, const float* __restrict__ p3,
    const float* __restrict__ p4, const float* __restrict__ p5,
    const float* __restrict__ p6, const float* __restrict__ proposals,
    float* __restrict__ out)
{
    const int roi = blockIdx.x;          // b * 512 + r
    const int b   = roi >> 9;
    const int tx  = threadIdx.x;         // 0..63 channel group
    const int oh  = threadIdx.y;         // 0..6 output row

    __shared__ int   s_y0[NS], s_x0[NS];
    __shared__ float s_ly[NS], s_lx[NS];
    __shared__ unsigned s_yvalid, s_xvalid;
    __shared__ const float* s_feat;
    __shared__ int s_H;

    const int flat = threadIdx.y * CG + threadIdx.x;

    // ---- coordinate setup: entire warp 0, no divergent collectives ----
    if (flat < 32) {
        // every lane redundantly computes the box/level scalars (cheap, uniform)
        const float* box = proposals + (size_t)roi * 4;
        float x1 = box[0], y1 = box[1], x2 = box[2], y2 = box[3];

        float w = fmaxf(x2 - x1, 1.0f);
        float h = fmaxf(y2 - y1, 1.0f);
        float lvlf = floorf(4.0f + log2f(sqrtf(w * h) / 224.0f));
        int lvl = (int)fminf(fmaxf(lvlf, 2.0f), 6.0f);   // 2..6

        int H = 1024 >> lvl;
        float Hf = (float)H;
        float scale = 1.0f / (float)(1 << lvl);

        float x1s = x1 * scale, y1s = y1 * scale;
        float bin_w = fmaxf(x2 * scale - x1s, 1.0f) / (float)OUT_HW;
        float bin_h = fmaxf(y2 * scale - y1s, 1.0f) / (float)OUT_HW;

        // lanes 0..13 handle one sample coordinate; lanes 14..31 passive
        const int j = (flat < NS) ? flat : (NS - 1);
        float sub = ((float)(j & 1) + 0.5f) * 0.5f;   // {0.25, 0.75}
        float pos = (float)(j >> 1) + sub;
        float Y = y1s + pos * bin_h;
        float X = x1s + pos * bin_w;

        bool lane_ok = (flat < NS);
        unsigned yv = __ballot_sync(0xffffffffu, lane_ok && Y >= -1.0f && Y <= Hf);
        unsigned xv = __ballot_sync(0xffffffffu, lane_ok && X >= -1.0f && X <= Hf);

        if (flat == 0) {
            const float* feats[5] = {p2, p3, p4, p5, p6};
            s_feat = feats[lvl - 2] + (size_t)b * H * H * CCH;
            s_H = H;
            s_yvalid = yv;
            s_xvalid = xv;
        }
        if (lane_ok) {
            float y = fminf(fmaxf(Y, 0.0f), Hf - 1.0f);
            float x = fminf(fmaxf(X, 0.0f), Hf - 1.0f);
            float y0 = floorf(y), x0 = floorf(x);
            s_y0[j] = (int)y0;  s_x0[j] = (int)x0;
            s_ly[j] = y - y0;   s_lx[j] = x - x0;
        }
    }
    __syncthreads();

    const float* feat = s_feat;
    const int H = s_H;
    const unsigned yvalid = s_yvalid, xvalid = s_xvalid;
    const int cb = tx * 4;               // channel base

    // two y-samples for this output row
    const int iy0 = oh * 2, iy1 = oh * 2 + 1;
    const int ya0 = s_y0[iy0];
    const int ya1 = s_y0[iy1];
    const int yb0 = min(ya0 + 1, H - 1);
    const int yb1 = min(ya1 + 1, H - 1);
    const float ly0 = s_ly[iy0], hy0 = 1.0f - ly0;
    const float ly1 = s_ly[iy1], hy1 = 1.0f - ly1;
    const bool yok0 = (yvalid >> iy0) & 1u;
    const bool yok1 = (yvalid >> iy1) & 1u;

    const float* rowA0 = feat + (size_t)ya0 * H * CCH + cb;
    const float* rowB0 = feat + (size_t)yb0 * H * CCH + cb;
    const float* rowA1 = feat + (size_t)ya1 * H * CCH + cb;
    const float* rowB1 = feat + (size_t)yb1 * H * CCH + cb;

    float* orow = out + ((size_t)roi * (OUT_HW * OUT_HW) + oh * OUT_HW) * CCH + cb;

    #pragma unroll
    for (int ow = 0; ow < OUT_HW; ow++) {
        const int ix0 = ow * 2, ix1 = ow * 2 + 1;
        const int xa0 = s_x0[ix0];
        const int xa1 = s_x0[ix1];
        const int xb0 = min(xa0 + 1, H - 1);
        const int xb1 = min(xa1 + 1, H - 1);
        const float lx0 = s_lx[ix0], hx0 = 1.0f - lx0;
        const float lx1 = s_lx[ix1], hx1 = 1.0f - lx1;
        const bool xok0 = (xvalid >> ix0) & 1u;
        const bool xok1 = (xvalid >> ix1) & 1u;

        float4 acc = make_float4(0.f, 0.f, 0.f, 0.f);

        if (yok0 & xok0) {   // sample (iy0, ix0)
            float4 v00 = *(const float4*)(rowA0 + (size_t)xa0 * CCH);
            float4 v01 = *(const float4*)(rowA0 + (size_t)xb0 * CCH);
            float4 v10 = *(const float4*)(rowB0 + (size_t)xa0 * CCH);
            float4 v11 = *(const float4*)(rowB0 + (size_t)xb0 * CCH);
            acc = f4fma(hy0 * hx0, v00, acc);
            acc = f4fma(hy0 * lx0, v01, acc);
            acc = f4fma(ly0 * hx0, v10, acc);
            acc = f4fma(ly0 * lx0, v11, acc);
        }
        if (yok0 & xok1) {   // sample (iy0, ix1)
            float4 v00 = *(const float4*)(rowA0 + (size_t)xa1 * CCH);
            float4 v01 = *(const float4*)(rowA0 + (size_t)xb1 * CCH);
            float4 v10 = *(const float4*)(rowB0 + (size_t)xa1 * CCH);
            float4 v11 = *(const float4*)(rowB0 + (size_t)xb1 * CCH);
            acc = f4fma(hy0 * hx1, v00, acc);
            acc = f4fma(hy0 * lx1, v01, acc);
            acc = f4fma(ly0 * hx1, v10, acc);
            acc = f4fma(ly0 * lx1, v11, acc);
        }
        if (yok1 & xok0) {   // sample (iy1, ix0)
            float4 v00 = *(const float4*)(rowA1 + (size_t)xa0 * CCH);
            float4 v01 = *(const float4*)(rowA1 + (size_t)xb0 * CCH);
            float4 v10 = *(const float4*)(rowB1 + (size_t)xa0 * CCH);
            float4 v11 = *(const float4*)(rowB1 + (size_t)xb0 * CCH);
            acc = f4fma(hy1 * hx0, v00, acc);
            acc = f4fma(hy1 * lx0, v01, acc);
            acc = f4fma(ly1 * hx0, v10, acc);
            acc = f4fma(ly1 * lx0, v11, acc);
        }
        if (yok1 & xok1) {   // sample (iy1, ix1)
            float4 v00 = *(const float4*)(rowA1 + (size_t)xa1 * CCH);
            float4 v01 = *(const float4*)(rowA1 + (size_t)xb1 * CCH);
            float4 v10 = *(const float4*)(rowB1 + (size_t)xa1 * CCH);
            float4 v11 = *(const float4*)(rowB1 + (size_t)xb1 * CCH);
            acc = f4fma(hy1 * hx1, v00, acc);
            acc = f4fma(hy1 * lx1, v01, acc);
            acc = f4fma(ly1 * hx1, v10, acc);
            acc = f4fma(ly1 * lx1, v11, acc);
        }

        acc.x *= 0.25f; acc.y *= 0.25f; acc.z *= 0.25f; acc.w *= 0.25f;
        *(float4*)(orow + ow * CCH) = acc;
    }
}

extern "C" void kernel_launch(void* const* d_in, const int* in_sizes, int n_in,
                              void* d_out, int out_size) {
    // Identify inputs by element count (all distinct):
    // p2=33554432, p3=8388608, p4=2097152, p5=524288, p6=131072, proposals=4096
    const float* ptr[6] = {nullptr, nullptr, nullptr, nullptr, nullptr, nullptr};
    int num_rois = 1024;
    for (int i = 0; i < n_in && i < 6; i++) {
        switch (in_sizes[i]) {
            case 33554432: ptr[0] = (const float*)d_in[i]; break;  // p2
            case 8388608:  ptr[1] = (const float*)d_in[i]; break;  // p3
            case 2097152:  ptr[2] = (const float*)d_in[i]; break;  // p4
            case 524288:   ptr[3] = (const float*)d_in[i]; break;  // p5
            case 131072:   ptr[4] = (const float*)d_in[i]; break;  // p6
            default:       ptr[5] = (const float*)d_in[i];
                           num_rois = in_sizes[i] / 4;     break;  // proposals
        }
    }

    dim3 block(CG, OUT_HW, 1);   // 64 x 7 = 448 threads
    roialign_fpn_kernel<<<num_rois, block>>>(ptr[0], ptr[1], ptr[2], ptr[3],
                                             ptr[4], ptr[5], (float*)d_out);
}

// round 5
// speedup vs baseline: 1.1993x; 1.1993x over previous
#include <cuda_runtime.h>
#include <math.h>

// BaseRoIHead multi-level RoIAlign (torchvision-style, aligned=False)
// B=2, R=512, C=256, out 7x7, sampling_ratio=2, levels p2..p6 (strides 4..64).
//
//  - one CTA per (roi, out-row): grid (1024, 7), 64 threads = 1 float4 group
//  - branchless: validity + 0.25 mean folded into precomputed shared weights,
//    all 16 gathers per bin unconditional (clamped indices always in-bounds)
//  - small CTAs (64 thr, <=56 regs) -> 18 CTAs/SM resident, 1152 threads/SM

#define OUT_HW 7
#define NS (OUT_HW * 2)    // 14 x-sample coords
#define CCH 256
#define CG  (CCH / 4)      // 64 float4 channel groups

__device__ __forceinline__ float4 f4fma(float s, float4 v, float4 a) {
    a.x = fmaf(s, v.x, a.x); a.y = fmaf(s, v.y, a.y);
    a.z = fmaf(s, v.z, a.z); a.w = fmaf(s, v.w, a.w);
    return a;
}

__global__ __launch_bounds__(CG, 18) void roialign_fpn_kernel(
    const float* __restrict__ p2, const float* __restrict__ p3,
    const float* __restrict__ p4, const float* __restrict__ p5,
    const float* __restrict__ p6, const float* __restrict__ proposals,
    float* __restrict__ out)
{
    const int roi = blockIdx.x;          // b * 512 + r
    const int oh  = blockIdx.y;          // output row 0..6
    const int b   = roi >> 9;
    const int tx  = threadIdx.x;         // 0..63 channel group

    __shared__ int   s_xoa[NS], s_xob[NS];     // x-tap element offsets (c-stride folded)
    __shared__ float s_hx[NS], s_lx[NS];       // masked x weights
    __shared__ int   s_rowoff[4];              // rowA0,rowB0,rowA1,rowB1 elem offsets
    __shared__ float s_wy[4];                  // masked y weights * 0.25
    __shared__ const float* s_feat;

    if (tx < 32) {
        // every lane computes the uniform box/level scalars
        const float* box = proposals + (size_t)roi * 4;
        float bx1 = box[0], by1 = box[1], bx2 = box[2], by2 = box[3];

        float w = fmaxf(bx2 - bx1, 1.0f);
        float h = fmaxf(by2 - by1, 1.0f);
        float lvlf = floorf(4.0f + log2f(sqrtf(w * h) / 224.0f));
        int lvl = (int)fminf(fmaxf(lvlf, 2.0f), 6.0f);   // 2..6

        int H = 1024 >> lvl;
        float Hf = (float)H;
        float scale = 1.0f / (float)(1 << lvl);

        float x1s = bx1 * scale, y1s = by1 * scale;
        float bin_w = fmaxf(bx2 * scale - x1s, 1.0f) / (float)OUT_HW;
        float bin_h = fmaxf(by2 * scale - y1s, 1.0f) / (float)OUT_HW;

        if (tx < NS) {
            // lanes 0..13: one x-sample each
            const int j = tx;
            float pos = (float)(j >> 1) + ((float)(j & 1) + 0.5f) * 0.5f;
            float X = x1s + pos * bin_w;
            bool ok = (X >= -1.0f) && (X <= Hf);
            float x = fminf(fmaxf(X, 0.0f), Hf - 1.0f);
            float x0 = floorf(x);
            int xa = (int)x0;
            int xb = min(xa + 1, H - 1);
            float lx = x - x0;
            s_xoa[j] = xa * CCH;
            s_xob[j] = xb * CCH;
            s_hx[j] = ok ? (1.0f - lx) : 0.0f;
            s_lx[j] = ok ? lx : 0.0f;
        } else if (tx == 16 || tx == 17) {
            // lanes 16,17: the two y-samples of this output row
            const int k = tx - 16;
            const int iy = oh * 2 + k;
            float pos = (float)(iy >> 1) + ((float)(iy & 1) + 0.5f) * 0.5f;
            float Y = y1s + pos * bin_h;
            bool ok = (Y >= -1.0f) && (Y <= Hf);
            float y = fminf(fmaxf(Y, 0.0f), Hf - 1.0f);
            float y0 = floorf(y);
            int ya = (int)y0;
            int yb = min(ya + 1, H - 1);
            float ly = y - y0;
            s_rowoff[2 * k]     = ya * H * CCH;
            s_rowoff[2 * k + 1] = yb * H * CCH;
            s_wy[2 * k]     = ok ? (1.0f - ly) * 0.25f : 0.0f;
            s_wy[2 * k + 1] = ok ? ly * 0.25f : 0.0f;
        } else if (tx == 31) {
            const float* feats[5] = {p2, p3, p4, p5, p6};
            s_feat = feats[lvl - 2] + (size_t)b * H * H * CCH;
        }
    }
    __syncthreads();

    const int cb = tx * 4;
    const float* base = s_feat + cb;
    const float* rA0 = base + s_rowoff[0];
    const float* rB0 = base + s_rowoff[1];
    const float* rA1 = base + s_rowoff[2];
    const float* rB1 = base + s_rowoff[3];
    const float wy0 = s_wy[0], wy1 = s_wy[1], wy2 = s_wy[2], wy3 = s_wy[3];

    float* orow = out + ((size_t)roi * (OUT_HW * OUT_HW) + oh * OUT_HW) * CCH + cb;

    #pragma unroll
    for (int ow = 0; ow < OUT_HW; ow++) {
        const int j0 = ow * 2, j1 = ow * 2 + 1;
        const int oa0 = s_xoa[j0], ob0 = s_xob[j0];
        const int oa1 = s_xoa[j1], ob1 = s_xob[j1];
        const float hx0 = s_hx[j0], lx0 = s_lx[j0];
        const float hx1 = s_hx[j1], lx1 = s_lx[j1];

        // 16 unconditional coalesced gathers (64 lanes x 16B = 1KB each)
        float4 vA0a0 = *(const float4*)(rA0 + oa0);
        float4 vA0b0 = *(const float4*)(rA0 + ob0);
        float4 vA0a1 = *(const float4*)(rA0 + oa1);
        float4 vA0b1 = *(const float4*)(rA0 + ob1);
        float4 vB0a0 = *(const float4*)(rB0 + oa0);
        float4 vB0b0 = *(const float4*)(rB0 + ob0);
        float4 vB0a1 = *(const float4*)(rB0 + oa1);
        float4 vB0b1 = *(const float4*)(rB0 + ob1);
        float4 vA1a0 = *(const float4*)(rA1 + oa0);
        float4 vA1b0 = *(const float4*)(rA1 + ob0);
        float4 vA1a1 = *(const float4*)(rA1 + oa1);
        float4 vA1b1 = *(const float4*)(rA1 + ob1);
        float4 vB1a0 = *(const float4*)(rB1 + oa0);
        float4 vB1b0 = *(const float4*)(rB1 + ob0);
        float4 vB1a1 = *(const float4*)(rB1 + oa1);
        float4 vB1b1 = *(const float4*)(rB1 + ob1);

        float4 acc = make_float4(0.f, 0.f, 0.f, 0.f);
        acc = f4fma(wy0 * hx0, vA0a0, acc);
        acc = f4fma(wy0 * lx0, vA0b0, acc);
        acc = f4fma(wy0 * hx1, vA0a1, acc);
        acc = f4fma(wy0 * lx1, vA0b1, acc);
        acc = f4fma(wy1 * hx0, vB0a0, acc);
        acc = f4fma(wy1 * lx0, vB0b0, acc);
        acc = f4fma(wy1 * hx1, vB0a1, acc);
        acc = f4fma(wy1 * lx1, vB0b1, acc);
        acc = f4fma(wy2 * hx0, vA1a0, acc);
        acc = f4fma(wy2 * lx0, vA1b0, acc);
        acc = f4fma(wy2 * hx1, vA1a1, acc);
        acc = f4fma(wy2 * lx1, vA1b1, acc);
        acc = f4fma(wy3 * hx0, vB1a0, acc);
        acc = f4fma(wy3 * lx0, vB1b0, acc);
        acc = f4fma(wy3 * hx1, vB1a1, acc);
        acc = f4fma(wy3 * lx1, vB1b1, acc);

        *(float4*)(orow + ow * CCH) = acc;
    }
}

extern "C" void kernel_launch(void* const* d_in, const int* in_sizes, int n_in,
                              void* d_out, int out_size) {
    // Identify inputs by element count (all distinct):
    // p2=33554432, p3=8388608, p4=2097152, p5=524288, p6=131072, proposals=4096
    const float* ptr[6] = {nullptr, nullptr, nullptr, nullptr, nullptr, nullptr};
    int num_rois = 1024;
    for (int i = 0; i < n_in && i < 6; i++) {
        switch (in_sizes[i]) {
            case 33554432: ptr[0] = (const float*)d_in[i]; break;  // p2
            case 8388608:  ptr[1] = (const float*)d_in[i]; break;  // p3
            case 2097152:  ptr[2] = (const float*)d_in[i]; break;  // p4
            case 524288:   ptr[3] = (const float*)d_in[i]; break;  // p5
            case 131072:   ptr[4] = (const float*)d_in[i]; break;  // p6
            default:       ptr[5] = (const float*)d_in[i];
                           num_rois = in_sizes[i] / 4;     break;  // proposals
        }
    }

    dim3 grid(num_rois, OUT_HW, 1);
    roialign_fpn_kernel<<<grid, CG>>>(ptr[0], ptr[1], ptr[2], ptr[3],
                                      ptr[4], ptr[5], (float*)d_out);
}

// round 6
// speedup vs baseline: 1.2000x; 1.0006x over previous
#include <cuda_runtime.h>
#include <math.h>

// BaseRoIHead multi-level RoIAlign (torchvision-style, aligned=False)
// B=2, R=512, C=256, out 7x7, sampling_ratio=2, levels p2..p6 (strides 4..64).
//
//  - one CTA per (roi, out-row): grid (1024, 7), 64 threads = 1 float4 group
//  - branchless: validity + 0.25 mean folded into precomputed shared weights,
//    all 16 gathers per bin unconditional (clamped indices always in-bounds)
//  - small CTAs (64 thr, <=56 regs) -> 18 CTAs/SM resident, 1152 threads/SM

#define OUT_HW 7
#define NS (OUT_HW * 2)    // 14 x-sample coords
#define CCH 256
#define CG  (CCH / 4)      // 64 float4 channel groups

__device__ __forceinline__ float4 f4fma(float s, float4 v, float4 a) {
    a.x = fmaf(s, v.x, a.x); a.y = fmaf(s, v.y, a.y);
    a.z = fmaf(s, v.z, a.z); a.w = fmaf(s, v.w, a.w);
    return a;
}

__global__ __launch_bounds__(CG, 18) void roialign_fpn_kernel(
    const float* __restrict__ p2, const float* __restrict__ p3,
    const float* __restrict__ p4, const float* __restrict__ p5,
    const float* __restrict__ p6, const float* __restrict__ proposals,
    float* __restrict__ out)
{
    const int roi = blockIdx.x;          // b * 512 + r
    const int oh  = blockIdx.y;          // output row 0..6
    const int b   = roi >> 9;
    const int tx  = threadIdx.x;         // 0..63 channel group

    __shared__ int   s_xoa[NS], s_xob[NS];     // x-tap element offsets (c-stride folded)
    __shared__ float s_hx[NS], s_lx[NS];       // masked x weights
    __shared__ int   s_rowoff[4];              // rowA0,rowB0,rowA1,rowB1 elem offsets
    __shared__ float s_wy[4];                  // masked y weights * 0.25
    __shared__ const float* s_feat;

    if (tx < 32) {
        // every lane computes the uniform box/level scalars
        const float* box = proposals + (size_t)roi * 4;
        float bx1 = box[0], by1 = box[1], bx2 = box[2], by2 = box[3];

        float w = fmaxf(bx2 - bx1, 1.0f);
        float h = fmaxf(by2 - by1, 1.0f);
        float lvlf = floorf(4.0f + log2f(sqrtf(w * h) / 224.0f));
        int lvl = (int)fminf(fmaxf(lvlf, 2.0f), 6.0f);   // 2..6

        int H = 1024 >> lvl;
        float Hf = (float)H;
        float scale = 1.0f / (float)(1 << lvl);

        float x1s = bx1 * scale, y1s = by1 * scale;
        float bin_w = fmaxf(bx2 * scale - x1s, 1.0f) / (float)OUT_HW;
        float bin_h = fmaxf(by2 * scale - y1s, 1.0f) / (float)OUT_HW;

        if (tx < NS) {
            // lanes 0..13: one x-sample each
            const int j = tx;
            float pos = (float)(j >> 1) + ((float)(j & 1) + 0.5f) * 0.5f;
            float X = x1s + pos * bin_w;
            bool ok = (X >= -1.0f) && (X <= Hf);
            float x = fminf(fmaxf(X, 0.0f), Hf - 1.0f);
            float x0 = floorf(x);
            int xa = (int)x0;
            int xb = min(xa + 1, H - 1);
            float lx = x - x0;
            s_xoa[j] = xa * CCH;
            s_xob[j] = xb * CCH;
            s_hx[j] = ok ? (1.0f - lx) : 0.0f;
            s_lx[j] = ok ? lx : 0.0f;
        } else if (tx == 16 || tx == 17) {
            // lanes 16,17: the two y-samples of this output row
            const int k = tx - 16;
            const int iy = oh * 2 + k;
            float pos = (float)(iy >> 1) + ((float)(iy & 1) + 0.5f) * 0.5f;
            float Y = y1s + pos * bin_h;
            bool ok = (Y >= -1.0f) && (Y <= Hf);
            float y = fminf(fmaxf(Y, 0.0f), Hf - 1.0f);
            float y0 = floorf(y);
            int ya = (int)y0;
            int yb = min(ya + 1, H - 1);
            float ly = y - y0;
            s_rowoff[2 * k]     = ya * H * CCH;
            s_rowoff[2 * k + 1] = yb * H * CCH;
            s_wy[2 * k]     = ok ? (1.0f - ly) * 0.25f : 0.0f;
            s_wy[2 * k + 1] = ok ? ly * 0.25f : 0.0f;
        } else if (tx == 31) {
            const float* feats[5] = {p2, p3, p4, p5, p6};
            s_feat = feats[lvl - 2] + (size_t)b * H * H * CCH;
        }
    }
    __syncthreads();

    const int cb = tx * 4;
    const float* base = s_feat + cb;
    const float* rA0 = base + s_rowoff[0];
    const float* rB0 = base + s_rowoff[1];
    const float* rA1 = base + s_rowoff[2];
    const float* rB1 = base + s_rowoff[3];
    const float wy0 = s_wy[0], wy1 = s_wy[1], wy2 = s_wy[2], wy3 = s_wy[3];

    float* orow = out + ((size_t)roi * (OUT_HW * OUT_HW) + oh * OUT_HW) * CCH + cb;

    #pragma unroll
    for (int ow = 0; ow < OUT_HW; ow++) {
        const int j0 = ow * 2, j1 = ow * 2 + 1;
        const int oa0 = s_xoa[j0], ob0 = s_xob[j0];
        const int oa1 = s_xoa[j1], ob1 = s_xob[j1];
        const float hx0 = s_hx[j0], lx0 = s_lx[j0];
        const float hx1 = s_hx[j1], lx1 = s_lx[j1];

        // 16 unconditional coalesced gathers (64 lanes x 16B = 1KB each)
        float4 vA0a0 = *(const float4*)(rA0 + oa0);
        float4 vA0b0 = *(const float4*)(rA0 + ob0);
        float4 vA0a1 = *(const float4*)(rA0 + oa1);
        float4 vA0b1 = *(const float4*)(rA0 + ob1);
        float4 vB0a0 = *(const float4*)(rB0 + oa0);
        float4 vB0b0 = *(const float4*)(rB0 + ob0);
        float4 vB0a1 = *(const float4*)(rB0 + oa1);
        float4 vB0b1 = *(const float4*)(rB0 + ob1);
        float4 vA1a0 = *(const float4*)(rA1 + oa0);
        float4 vA1b0 = *(const float4*)(rA1 + ob0);
        float4 vA1a1 = *(const float4*)(rA1 + oa1);
        float4 vA1b1 = *(const float4*)(rA1 + ob1);
        float4 vB1a0 = *(const float4*)(rB1 + oa0);
        float4 vB1b0 = *(const float4*)(rB1 + ob0);
        float4 vB1a1 = *(const float4*)(rB1 + oa1);
        float4 vB1b1 = *(const float4*)(rB1 + ob1);

        float4 acc = make_float4(0.f, 0.f, 0.f, 0.f);
        acc = f4fma(wy0 * hx0, vA0a0, acc);
        acc = f4fma(wy0 * lx0, vA0b0, acc);
        acc = f4fma(wy0 * hx1, vA0a1, acc);
        acc = f4fma(wy0 * lx1, vA0b1, acc);
        acc = f4fma(wy1 * hx0, vB0a0, acc);
        acc = f4fma(wy1 * lx0, vB0b0, acc);
        acc = f4fma(wy1 * hx1, vB0a1, acc);
        acc = f4fma(wy1 * lx1, vB0b1, acc);
        acc = f4fma(wy2 * hx0, vA1a0, acc);
        acc = f4fma(wy2 * lx0, vA1b0, acc);
        acc = f4fma(wy2 * hx1, vA1a1, acc);
        acc = f4fma(wy2 * lx1, vA1b1, acc);
        acc = f4fma(wy3 * hx0, vB1a0, acc);
        acc = f4fma(wy3 * lx0, vB1b0, acc);
        acc = f4fma(wy3 * hx1, vB1a1, acc);
        acc = f4fma(wy3 * lx1, vB1b1, acc);

        *(float4*)(orow + ow * CCH) = acc;
    }
}

extern "C" void kernel_launch(void* const* d_in, const int* in_sizes, int n_in,
                              void* d_out, int out_size) {
    // Identify inputs by element count (all distinct):
    // p2=33554432, p3=8388608, p4=2097152, p5=524288, p6=131072, proposals=4096
    const float* ptr[6] = {nullptr, nullptr, nullptr, nullptr, nullptr, nullptr};
    int num_rois = 1024;
    for (int i = 0; i < n_in && i < 6; i++) {
        switch (in_sizes[i]) {
            case 33554432: ptr[0] = (const float*)d_in[i]; break;  // p2
            case 8388608:  ptr[1] = (const float*)d_in[i]; break;  // p3
            case 2097152:  ptr[2] = (const float*)d_in[i]; break;  // p4
            case 524288:   ptr[3] = (const float*)d_in[i]; break;  // p5
            case 131072:   ptr[4] = (const float*)d_in[i]; break;  // p6
            default:       ptr[5] = (const float*)d_in[i];
                           num_rois = in_sizes[i] / 4;     break;  // proposals
        }
    }

    dim3 grid(num_rois, OUT_HW, 1);
    roialign_fpn_kernel<<<grid, CG>>>(ptr[0], ptr[1], ptr[2], ptr[3],
                                      ptr[4], ptr[5], (float*)d_out);
}